// round 4
// baseline (speedup 1.0000x reference)
#include <cuda_runtime.h>
#include <math.h>

#define HID 128
#define NNODES 50000
#define NREL 500
#define NEDGES 625000
#define LDS_ (HID + 4)                       // padded smem stride (132 floats)
#define SMEM_BYTES (2 * HID * LDS_ * 4)      // As + Bs = 135168 B

// ---------------- scratch (device globals; no allocation allowed) ----------------
__device__ __align__(16) float g_xpart[NNODES * HID];   // x @ W_mess[:, :H]^T + b_mess
__device__ __align__(16) float g_rnorm[NREL * HID];     // batch-normed relations
__device__ __align__(16) float g_rpart[NREL * HID];     // rnorm @ W_mess[:, H:]^T
__device__ float g_cq[HID];                              // W_matt[:, H:] @ qc + b_matt
__device__ float g_cf[HID];                              // W_xatt[:, H:] @ fq + b_xatt
__device__ float g_coeff[NEDGES];
__device__ float g_segsum[NNODES];
__device__ __align__(16) float g_sum_un[NNODES * HID];  // unnormalized weighted message sum

__device__ __forceinline__ float lrelu(float z) { return z > 0.f ? z : 0.01f * z; }

// scalar global float reduction via inline PTX (no compiler re-vectorization)
__device__ __forceinline__ void red_add_f32(float* ptr, float val) {
    asm volatile("red.global.add.f32 [%0], %1;" :: "l"(ptr), "f"(val) : "memory");
}

// ---------------- init scratch ----------------
__global__ void init_kernel() {
    int stride = gridDim.x * blockDim.x;
    for (int i = blockIdx.x * blockDim.x + threadIdx.x; i < NNODES * HID; i += stride)
        g_sum_un[i] = 0.f;
    for (int i = blockIdx.x * blockDim.x + threadIdx.x; i < NNODES; i += stride)
        g_segsum[i] = 0.f;
}

// ---------------- BatchNorm1d over relations (training-mode batch stats) ----------------
__global__ void bn_kernel(const float* __restrict__ r, const float* __restrict__ gamma,
                          const float* __restrict__ beta, float* __restrict__ out_r) {
    int j = threadIdx.x;   // column
    float s = 0.f;
    for (int i = 0; i < NREL; i++) s += r[i * HID + j];
    float mu = s / (float)NREL;
    float v = 0.f;
    for (int i = 0; i < NREL; i++) { float d = r[i * HID + j] - mu; v += d * d; }
    v /= (float)NREL;
    float sc = rsqrtf(v + 1e-5f) * gamma[j];
    float bi = beta[j];
    for (int i = 0; i < NREL; i++) {
        float val = (r[i * HID + j] - mu) * sc + bi;
        g_rnorm[i * HID + j] = val;
        out_r[i * HID + j]   = val;
    }
}

// ---------------- constant vectors from que_context / fin_que ----------------
__global__ void const_kernel(const float* __restrict__ W_matt, const float* __restrict__ b_matt,
                             const float* __restrict__ qc,
                             const float* __restrict__ W_xatt, const float* __restrict__ b_xatt,
                             const float* __restrict__ fq) {
    __shared__ float q_s[HID], f_s[HID];
    int t = threadIdx.x;
    q_s[t] = qc[t];
    f_s[t] = fq[t];
    __syncthreads();
    float s1 = b_matt[t], s2 = b_xatt[t];
    for (int c = 0; c < HID; c++) {
        s1 += W_matt[t * 2 * HID + HID + c] * q_s[c];
        s2 += W_xatt[t * 2 * HID + HID + c] * f_s[c];
    }
    g_cq[t] = s1;
    g_cf[t] = s2;
}

// ---------------- C[M,128] = A[M,128] @ W[:, off:off+128]^T (+bias) ----------------
__global__ void gemm_at(const float* __restrict__ A_in, const float* __restrict__ W,
                        const float* __restrict__ bias_in, int mode) {
    extern __shared__ float sm[];
    float* As = sm;              // As[c*LDS_+row]
    float* Bs = sm + HID * LDS_; // Bs[c*LDS_+h] = W[h][off+c]
    const float* A   = mode ? g_rnorm : A_in;
    float*       C   = mode ? g_rpart : g_xpart;
    const float* bias= mode ? (const float*)nullptr : bias_in;
    int off = mode ? HID : 0;
    int M   = mode ? NREL : NNODES;

    int r0 = blockIdx.x * 128;
    int valid = min(128, M - r0);
    int t = threadIdx.x;
    for (int idx = t; idx < 128 * HID; idx += 256) {
        int rl = idx >> 7, c = idx & 127;
        float v = (rl < valid) ? A[(r0 + rl) * HID + c] : 0.f;
        As[c * LDS_ + rl] = v;
        Bs[c * LDS_ + rl] = W[rl * (2 * HID) + off + c];  // rl reused as h
    }
    __syncthreads();

    int te = t >> 4, th = t & 15;
    float acc[8][8];
#pragma unroll
    for (int i = 0; i < 8; i++)
#pragma unroll
        for (int j = 0; j < 8; j++) acc[i][j] = 0.f;

#pragma unroll 4
    for (int c = 0; c < HID; c++) {
        float4 a0 = *(float4*)&As[c * LDS_ + te * 8];
        float4 a1 = *(float4*)&As[c * LDS_ + te * 8 + 4];
        float4 b0 = *(float4*)&Bs[c * LDS_ + th * 8];
        float4 b1 = *(float4*)&Bs[c * LDS_ + th * 8 + 4];
        float a[8] = {a0.x, a0.y, a0.z, a0.w, a1.x, a1.y, a1.z, a1.w};
        float b[8] = {b0.x, b0.y, b0.z, b0.w, b1.x, b1.y, b1.z, b1.w};
#pragma unroll
        for (int i = 0; i < 8; i++)
#pragma unroll
            for (int j = 0; j < 8; j++) acc[i][j] += a[i] * b[j];
    }

    float bb[8];
#pragma unroll
    for (int j = 0; j < 8; j++) bb[j] = bias ? bias[th * 8 + j] : 0.f;

#pragma unroll
    for (int i = 0; i < 8; i++) {
        int rl = te * 8 + i;
        if (rl < valid) {
            float4 o0, o1;
            o0.x = acc[i][0] + bb[0]; o0.y = acc[i][1] + bb[1];
            o0.z = acc[i][2] + bb[2]; o0.w = acc[i][3] + bb[3];
            o1.x = acc[i][4] + bb[4]; o1.y = acc[i][5] + bb[5];
            o1.z = acc[i][6] + bb[6]; o1.w = acc[i][7] + bb[7];
            *(float4*)&C[(r0 + rl) * HID + th * 8]     = o0;
            *(float4*)&C[(r0 + rl) * HID + th * 8 + 4] = o1;
        }
    }
}

// ---------------- per-edge attention logits ----------------
__global__ void edge_coeff_kernel(const int* __restrict__ eidx,
                                  const int* __restrict__ eattr,
                                  const float* __restrict__ W_matt,
                                  const float* __restrict__ w_att) {
    extern __shared__ float sm[];
    float* As = sm;               // mess, K-major: As[c*LDS_+e]
    float* Bs = sm + HID * LDS_;  // W_matt[:, :H] transposed
    __shared__ int head_s[128], attr_s[128];
    __shared__ float w_s[HID], cq_s[HID];

    int e0 = blockIdx.x * 128;
    int valid = min(128, NEDGES - e0);
    int t = threadIdx.x;
    if (t < 128) {
        if (t < valid) {
            head_s[t] = eidx[e0 + t];
            attr_s[t] = eattr[e0 + t];
        } else {
            head_s[t] = 0; attr_s[t] = 0;
        }
        w_s[t]  = w_att[t];
        cq_s[t] = g_cq[t];
    }
    __syncthreads();

    for (int idx = t; idx < 128 * HID; idx += 256) {
        int e = idx >> 7, c = idx & 127;
        As[c * LDS_ + e] = tanhf(g_xpart[head_s[e] * HID + c] + g_rpart[attr_s[e] * HID + c]);
        Bs[c * LDS_ + e] = W_matt[e * (2 * HID) + c];   // e reused as h
    }
    __syncthreads();

    int te = t >> 4, th = t & 15;
    float acc[8][8];
#pragma unroll
    for (int i = 0; i < 8; i++)
#pragma unroll
        for (int j = 0; j < 8; j++) acc[i][j] = 0.f;

#pragma unroll 4
    for (int c = 0; c < HID; c++) {
        float4 a0 = *(float4*)&As[c * LDS_ + te * 8];
        float4 a1 = *(float4*)&As[c * LDS_ + te * 8 + 4];
        float4 b0 = *(float4*)&Bs[c * LDS_ + th * 8];
        float4 b1 = *(float4*)&Bs[c * LDS_ + th * 8 + 4];
        float a[8] = {a0.x, a0.y, a0.z, a0.w, a1.x, a1.y, a1.z, a1.w};
        float b[8] = {b0.x, b0.y, b0.z, b0.w, b1.x, b1.y, b1.z, b1.w};
#pragma unroll
        for (int i = 0; i < 8; i++)
#pragma unroll
            for (int j = 0; j < 8; j++) acc[i][j] += a[i] * b[j];
    }

    float p[8] = {0.f, 0.f, 0.f, 0.f, 0.f, 0.f, 0.f, 0.f};
#pragma unroll
    for (int j = 0; j < 8; j++) {
        int h = th * 8 + j;
        float wj = w_s[h], cqj = cq_s[h];
#pragma unroll
        for (int i = 0; i < 8; i++) p[i] += wj * lrelu(acc[i][j] + cqj);
    }
#pragma unroll
    for (int k = 8; k >= 1; k >>= 1)
#pragma unroll
        for (int i = 0; i < 8; i++) p[i] += __shfl_xor_sync(0xffffffffu, p[i], k);

    if (th == 0) {
#pragma unroll
        for (int i = 0; i < 8; i++) {
            int rl = te * 8 + i;
            if (rl < valid) g_coeff[e0 + rl] = p[i];
        }
    }
}

// ---------------- exp + weighted scatter aggregation (one warp per edge) ----------------
// softmax without max-shift: logits are O(±8) here (tanh-bounded messages ×
// Xavier weights), exp() is safe; softmax is shift-invariant.
__global__ void aggregate_kernel(const int* __restrict__ eidx,
                                 const int* __restrict__ eattr) {
    int gw = (blockIdx.x * blockDim.x + threadIdx.x) >> 5;
    int lane = threadIdx.x & 31;
    int nw = (gridDim.x * blockDim.x) >> 5;
    for (int e = gw; e < NEDGES; e += nw) {
        int head = eidx[e];
        int tail = eidx[NEDGES + e];
        int rel  = eattr[e];
        float ec = expf(g_coeff[e]);
        const float* xp = &g_xpart[head * HID];
        const float* rp = &g_rpart[rel * HID];
        float* dst = &g_sum_un[tail * HID];
#pragma unroll
        for (int k = 0; k < 4; k++) {
            int h = lane + 32 * k;
            float v = tanhf(xp[h] + rp[h]) * ec;
            red_add_f32(dst + h, v);
        }
        if (lane == 0) red_add_f32(&g_segsum[tail], ec);
    }
}

// ---------------- per-node gating softmax + output ----------------
__global__ void node_out_kernel(const float* __restrict__ x, const float* __restrict__ W_xatt,
                                const float* __restrict__ w_xatt, float* __restrict__ out) {
    extern __shared__ float sm[];
    float* As = sm;               // rows: 2n=x[node], 2n+1=sum_mess[node]; K-major
    float* Bs = sm + HID * LDS_;
    __shared__ float invs[64], w0s[64], wx_s[HID], cf_s[HID];

    int n0 = blockIdx.x * 64;
    int valid = min(64, NNODES - n0);
    int t = threadIdx.x;
    if (t < 64) invs[t] = (t < valid) ? 1.f / (g_segsum[n0 + t] + 1e-16f) : 0.f;
    if (t < HID) { wx_s[t] = w_xatt[t]; cf_s[t] = g_cf[t]; }
    __syncthreads();

    for (int idx = t; idx < 64 * HID; idx += 256) {
        int nl = idx >> 7, c = idx & 127;
        float xv = 0.f, sv = 0.f;
        if (nl < valid) {
            int node = n0 + nl;
            xv = x[node * HID + c];
            sv = g_sum_un[node * HID + c] * invs[nl];
        }
        As[c * LDS_ + 2 * nl]     = xv;
        As[c * LDS_ + 2 * nl + 1] = sv;
    }
    for (int idx = t; idx < 128 * HID; idx += 256) {
        int h = idx >> 7, c = idx & 127;
        Bs[c * LDS_ + h] = W_xatt[h * (2 * HID) + c];
    }
    __syncthreads();

    int te = t >> 4, th = t & 15;
    float acc[8][8];
#pragma unroll
    for (int i = 0; i < 8; i++)
#pragma unroll
        for (int j = 0; j < 8; j++) acc[i][j] = 0.f;

#pragma unroll 4
    for (int c = 0; c < HID; c++) {
        float4 a0 = *(float4*)&As[c * LDS_ + te * 8];
        float4 a1 = *(float4*)&As[c * LDS_ + te * 8 + 4];
        float4 b0 = *(float4*)&Bs[c * LDS_ + th * 8];
        float4 b1 = *(float4*)&Bs[c * LDS_ + th * 8 + 4];
        float a[8] = {a0.x, a0.y, a0.z, a0.w, a1.x, a1.y, a1.z, a1.w};
        float b[8] = {b0.x, b0.y, b0.z, b0.w, b1.x, b1.y, b1.z, b1.w};
#pragma unroll
        for (int i = 0; i < 8; i++)
#pragma unroll
            for (int j = 0; j < 8; j++) acc[i][j] += a[i] * b[j];
    }

    float p[8] = {0.f, 0.f, 0.f, 0.f, 0.f, 0.f, 0.f, 0.f};
#pragma unroll
    for (int j = 0; j < 8; j++) {
        int h = th * 8 + j;
        float wj = wx_s[h], cfj = cf_s[h];
#pragma unroll
        for (int i = 0; i < 8; i++) p[i] += wj * lrelu(acc[i][j] + cfj);
    }
#pragma unroll
    for (int k = 8; k >= 1; k >>= 1)
#pragma unroll
        for (int i = 0; i < 8; i++) p[i] += __shfl_xor_sync(0xffffffffu, p[i], k);

    if (th == 0) {
#pragma unroll
        for (int i = 0; i < 8; i += 2) {
            int row = te * 8 + i;
            int nl = row >> 1;
            float p0 = p[i], p1 = p[i + 1];
            float mm = fmaxf(p0, p1);
            float ea = expf(p0 - mm), eb = expf(p1 - mm);
            w0s[nl] = ea / (ea + eb);
        }
    }
    __syncthreads();

    for (int idx = t; idx < 64 * HID; idx += 256) {
        int nl = idx >> 7, h = idx & 127;
        if (nl < valid) {
            float w0 = w0s[nl];
            out[(n0 + nl) * HID + h] =
                w0 * As[h * LDS_ + 2 * nl] + (1.f - w0) * As[h * LDS_ + 2 * nl + 1];
        }
    }
}

// ---------------- host launcher ----------------
extern "C" void kernel_launch(void* const* d_in, const int* in_sizes, int n_in,
                              void* d_out, int out_size) {
    const float* x      = (const float*)d_in[0];
    const float* r      = (const float*)d_in[1];
    const float* qc     = (const float*)d_in[2];
    const float* fq     = (const float*)d_in[3];
    const int*   ei     = (const int*)d_in[4];    // int32 (JAX default x64-disabled)
    const int*   ea     = (const int*)d_in[5];    // int32
    const float* W_mess = (const float*)d_in[6];
    const float* b_mess = (const float*)d_in[7];
    const float* W_matt = (const float*)d_in[8];
    const float* b_matt = (const float*)d_in[9];
    const float* w_matt = (const float*)d_in[10];
    const float* W_xatt = (const float*)d_in[11];
    const float* b_xatt = (const float*)d_in[12];
    const float* w_xatt = (const float*)d_in[13];
    const float* gamma  = (const float*)d_in[14];
    const float* beta   = (const float*)d_in[15];
    float* out = (float*)d_out;

    cudaFuncSetAttribute(gemm_at, cudaFuncAttributeMaxDynamicSharedMemorySize, SMEM_BYTES);
    cudaFuncSetAttribute(edge_coeff_kernel, cudaFuncAttributeMaxDynamicSharedMemorySize, SMEM_BYTES);
    cudaFuncSetAttribute(node_out_kernel, cudaFuncAttributeMaxDynamicSharedMemorySize, SMEM_BYTES);

    init_kernel<<<512, 256>>>();
    bn_kernel<<<1, 128>>>(r, gamma, beta, out + (size_t)NNODES * HID);
    const_kernel<<<1, 128>>>(W_matt, b_matt, qc, W_xatt, b_xatt, fq);
    gemm_at<<<(NNODES + 127) / 128, 256, SMEM_BYTES>>>(x, W_mess, b_mess, 0);
    gemm_at<<<(NREL + 127) / 128, 256, SMEM_BYTES>>>(nullptr, W_mess, nullptr, 1);
    edge_coeff_kernel<<<(NEDGES + 127) / 128, 256, SMEM_BYTES>>>(ei, ea, W_matt, w_matt);
    aggregate_kernel<<<2048, 256>>>(ei, ea);
    node_out_kernel<<<(NNODES + 63) / 64, 256, SMEM_BYTES>>>(x, W_xatt, w_xatt, out);
}